// round 6
// baseline (speedup 1.0000x reference)
#include <cuda_runtime.h>
#include <cuda_bf16.h>
#include <math.h>
#include <stdint.h>

#define B_  4
#define C_  64
#define HH  128
#define WW  128
#define F_  5
#define L_  512
#define NH_ 128

// ---------------- device scratch ----------------
__device__ float g_mu[B_*F_*L_];
__device__ unsigned char g_rmap[B_*HH*WW];
__device__ float g_Tg[B_*9*F_*C_];               // [b][tap][f][c]
__device__ float g_Tb[B_*9*F_*C_];
__device__ __nv_bfloat16 g_act[(size_t)B_*HH*WW*NH_];  // NHWC bf16
__device__ __nv_bfloat16 g_Aw[9*128*128];        // [tap][c128][nh] bf16
__device__ float g_mean[B_*C_];
__device__ float g_rsig[B_*C_];

// ---------------- helpers ----------------
__device__ __forceinline__ uint32_t smem_u32(const void* p) {
    uint32_t a;
    asm("{ .reg .u64 t; cvta.to.shared.u64 t, %1; cvt.u32.u64 %0, t; }" : "=r"(a) : "l"(p));
    return a;
}
__device__ __forceinline__ void cpa16(uint32_t dst, const void* src, uint32_t ssz) {
    asm volatile("cp.async.ca.shared.global [%0], [%1], 16, %2;"
                 :: "r"(dst), "l"(src), "r"(ssz) : "memory");
}
__device__ __forceinline__ void ldsm4(uint32_t* r, uint32_t addr) {
    asm volatile("ldmatrix.sync.aligned.m8n8.x4.shared.b16 {%0,%1,%2,%3}, [%4];"
        : "=r"(r[0]), "=r"(r[1]), "=r"(r[2]), "=r"(r[3]) : "r"(addr));
}
__device__ __forceinline__ void mma_bf16(float* d, const uint32_t* a, const uint32_t* b) {
    asm volatile("mma.sync.aligned.m16n8k16.row.col.f32.bf16.bf16.f32 "
        "{%0,%1,%2,%3},{%4,%5,%6,%7},{%8,%9},{%0,%1,%2,%3};"
        : "+f"(d[0]), "+f"(d[1]), "+f"(d[2]), "+f"(d[3])
        : "r"(a[0]), "r"(a[1]), "r"(a[2]), "r"(a[3]), "r"(b[0]), "r"(b[1]));
}

// ---------------- mu = relu(codes @ fc_w^T + fc_b) ----------------
__global__ void mu_kernel(const float* __restrict__ codes,
                          const float* __restrict__ fc_w,
                          const float* __restrict__ fc_b) {
    __shared__ float sc[L_];
    int bf = blockIdx.x;
    int f = bf % F_;
    int k = threadIdx.x;
    sc[k] = codes[bf*L_ + k];
    __syncthreads();
    const float* wp = fc_w + ((size_t)f*L_ + k)*L_;
    float acc = fc_b[f*L_ + k];
    #pragma unroll 4
    for (int l = 0; l < L_; ++l) acc = fmaf(sc[l], wp[l], acc);
    g_mu[bf*L_ + k] = fmaxf(acc, 0.f);
}

// ---------------- region map ----------------
__global__ void region_kernel(const float* __restrict__ seg) {
    int p = blockIdx.x*256 + threadIdx.x;
    if (p >= B_*HH*WW) return;
    int b = p >> 14, pix = p & 16383;
    int r = 5;
    #pragma unroll
    for (int j = 0; j < F_; ++j)
        if (seg[(b*F_ + j)*16384 + pix] > 0.f) r = j;
    g_rmap[p] = (unsigned char)r;
}

// ---------------- tables T[b,tap,f,c] ----------------
__global__ void table_kernel(const float* __restrict__ cgw,
                             const float* __restrict__ cbw) {
    int gt = blockIdx.x*256 + threadIdx.x;
    int e = gt >> 5, lane = gt & 31;
    int tbl = e / 11520; int r = e - tbl*11520;
    int b = r / 2880;    int r2 = r - b*2880;
    int tap = r2 / 320;  int r3 = r2 - tap*320;
    int f = r3 >> 6;     int c = r3 & 63;
    int dy = tap / 3, dx = tap - dy*3;
    const float* w = tbl ? cbw : cgw;
    const float* m = g_mu + (b*F_ + f)*L_;
    float s = 0.f;
    for (int l = lane; l < L_; l += 32)
        s = fmaf(w[(((size_t)c*L_ + l)*3 + dy)*3 + dx], m[l], s);
    #pragma unroll
    for (int o = 16; o > 0; o >>= 1) s += __shfl_down_sync(0xffffffffu, s, o);
    if (lane == 0)
        (tbl ? g_Tb : g_Tg)[((b*9 + tap)*F_ + f)*64 + c] = s;
}

// ---------------- instance norm stats ----------------
__global__ void stats_kernel(const float* __restrict__ x) {
    int bc = blockIdx.x;
    const float* p = x + (size_t)bc*16384;
    float s = 0.f, s2 = 0.f;
    for (int i = threadIdx.x; i < 16384; i += 256) {
        float v = p[i]; s += v; s2 = fmaf(v, v, s2);
    }
    __shared__ float sh1[256], sh2[256];
    sh1[threadIdx.x] = s; sh2[threadIdx.x] = s2;
    __syncthreads();
    for (int o = 128; o > 0; o >>= 1) {
        if (threadIdx.x < o) { sh1[threadIdx.x] += sh1[threadIdx.x+o]; sh2[threadIdx.x] += sh2[threadIdx.x+o]; }
        __syncthreads();
    }
    if (threadIdx.x == 0) {
        float m = sh1[0] * (1.f/16384.f);
        float var = sh2[0] * (1.f/16384.f) - m*m;
        g_mean[bc] = m;
        g_rsig[bc] = rsqrtf(var + 1e-5f);
    }
}

// ---------------- weight prep: bf16, layout [tap][c128][nh] ----------------
__global__ void wprep_kernel(const float* __restrict__ sgw,
                             const float* __restrict__ sbw) {
    int idx = blockIdx.x*256 + threadIdx.x;
    if (idx >= 9*128*128) return;
    int nh = idx & 127, c = (idx >> 7) & 127, tap = idx >> 14;
    const float* src = (c < 64) ? sgw : sbw;
    float v = src[(((c & 63)*128) + nh)*9 + tap];
    g_Aw[idx] = __float2bfloat16_rn(v);
}

// ---------------- SPADE shared conv -> NHWC bf16 ----------------
__global__ void sconv_kernel(const float* __restrict__ mask,
                             const float* __restrict__ w,
                             const float* __restrict__ bias) {
    __shared__ float sw[NH_*27];
    __shared__ float smk[3][3][34];
    int t = threadIdx.x;
    int b = blockIdx.z, y = blockIdx.y, x0 = blockIdx.x*32;
    for (int i = t; i < NH_*27; i += 256) sw[i] = w[i];
    for (int i = t; i < 3*3*34; i += 256) {
        int ch = i / 102, rem = i - ch*102;
        int r = rem / 34, cx = rem - r*34;
        int gy = y + r - 1, gx = x0 + cx - 1;
        float v = 0.f;
        if ((unsigned)gy < 128u && (unsigned)gx < 128u)
            v = mask[((b*3 + ch) << 14) + (gy << 7) + gx];
        smk[ch][r][cx] = v;
    }
    __syncthreads();
    int px = t >> 3, g = t & 7;
    float mv[3][3][3];
    #pragma unroll
    for (int ch = 0; ch < 3; ++ch)
        #pragma unroll
        for (int r = 0; r < 3; ++r)
            #pragma unroll
            for (int d = 0; d < 3; ++d)
                mv[ch][r][d] = smk[ch][r][px + d];
    int nh0 = g*16;
    unsigned hw[8];
    #pragma unroll 2
    for (int k = 0; k < 16; ++k) {
        int nh = nh0 + k;
        float acc = __ldg(&bias[nh]);
        const float* wp = &sw[nh*27];
        #pragma unroll
        for (int ch = 0; ch < 3; ++ch)
            #pragma unroll
            for (int r = 0; r < 3; ++r)
                #pragma unroll
                for (int d = 0; d < 3; ++d)
                    acc = fmaf(mv[ch][r][d], wp[ch*9 + r*3 + d], acc);
        acc = fmaxf(acc, 0.f);
        unsigned hb = (unsigned)__bfloat16_as_ushort(__float2bfloat16_rn(acc));
        if (k & 1) hw[k>>1] |= hb << 16;
        else       hw[k>>1]  = hb;
    }
    size_t base = (((size_t)(b*128 + y))*128 + (x0 + px))*128 + nh0;
    uint4* dh = (uint4*)&g_act[base];
    dh[0] = make_uint4(hw[0], hw[1], hw[2], hw[3]);
    dh[1] = make_uint4(hw[4], hw[5], hw[6], hw[7]);
}

// ---------------- fused HMMA conv + table gather + blend + denorm ----------------
// block = 1 image row (128 px), 256 threads (8 warps: 4M x 2N), M=128 couts.
// Single-term bf16, K = 9 taps x 128 nh, chunks of 32 (36 iters),
// 4-stage cp.async ring (2 bufs per stage: A weights, B actv), ldmatrix.
#define ROWB   80
#define A_H    0
#define B_H    10240
#define STG    20480
#define OFF_TG (4*STG)
#define OFF_TB (OFF_TG + 11520)
#define OFF_R  (OFF_TB + 11520)
#define DYN_BYTES (OFF_R + 512)

__global__ __launch_bounds__(256, 2) void final_kernel(
    const float* __restrict__ x_in,
    const float* __restrict__ sgb, const float* __restrict__ sbb,
    const float* __restrict__ cgb, const float* __restrict__ cbb,
    const float* __restrict__ bgam, const float* __restrict__ bbet,
    float* __restrict__ out)
{
    extern __shared__ char dsm[];
    uint32_t sb = smem_u32(dsm);
    float* sGB = (float*)dsm;                  // [128 c][132 px] epilogue (aliases stages)
    float* sTg = (float*)(dsm + OFF_TG);
    float* sTb = (float*)(dsm + OFF_TB);
    unsigned char* sR = (unsigned char*)(dsm + OFF_R);   // [3][132]

    int t = threadIdx.x, wid = t >> 5, lane = t & 31;
    int b = blockIdx.y, y = blockIdx.x;
    int wm = wid >> 1, wn = wid & 1, g = lane >> 2, tg = lane & 3;

    // prologue: tables + region halo
    for (int i = t; i < 2880; i += 256) {
        sTg[i] = g_Tg[b*2880 + i];
        sTb[i] = g_Tb[b*2880 + i];
    }
    for (int i = t; i < 3*132; i += 256) {
        int r = i / 132, cx = i - r*132;
        int gy = y - 1 + r, gx = cx - 1;
        unsigned char rr = 5;
        if (cx < 130 && (unsigned)gy < 128u && (unsigned)gx < 128u)
            rr = g_rmap[(b << 14) + (gy << 7) + gx];
        sR[i] = rr;
    }

    // ldmatrix lane address bases
    int rowA = wm*32 + (lane & 7) + ((lane >> 3) & 1)*8;
    int kbA  = (lane >> 4)*16;
    uint32_t aBase = sb + rowA*ROWB + kbA;
    int nB  = wn*64 + (lane & 7) + ((lane >> 4) & 1)*8;
    int kbB = ((lane >> 3) & 1)*16;
    uint32_t bBase = sb + nB*ROWB + kbB;

    // staging: chunk ck = (tap = ck>>2, kc = ck&3), K=32 nh values
    int srow = t >> 1, sseg2 = (t & 1)*2;
    auto stage = [&](int ck) {
        int s = ck & 3;
        int tap = ck >> 2, kc = ck & 3;
        int dyy = tap / 3, dxx = tap - 3*dyy;
        uint32_t base = sb + s*STG;
        int gy = y + dyy - 1, gx = srow + dxx - 1;
        bool in = ((unsigned)gy < 128u) && ((unsigned)gx < 128u);
        size_t bbase = (((size_t)(b*128 + (in ? gy : 0)))*128 + (in ? gx : 0))*128 + kc*32;
        uint32_t ssz = in ? 16u : 0u;
        size_t abase = (size_t)tap*16384 + srow*128 + kc*32;
        #pragma unroll
        for (int q = 0; q < 2; ++q) {
            int seg = sseg2 + q;
            uint32_t doff = srow*ROWB + seg*16;
            cpa16(base + A_H + doff, g_Aw + abase + seg*8, 16);
            cpa16(base + B_H + doff, g_act + bbase + seg*8, ssz);
        }
    };

    float acc[2][8][4];
    #pragma unroll
    for (int mt = 0; mt < 2; ++mt)
        #pragma unroll
        for (int nt = 0; nt < 8; ++nt)
            #pragma unroll
            for (int ci = 0; ci < 4; ++ci) acc[mt][nt][ci] = 0.f;

    stage(0);
    asm volatile("cp.async.commit_group;" ::: "memory");
    stage(1);
    asm volatile("cp.async.commit_group;" ::: "memory");
    stage(2);
    asm volatile("cp.async.commit_group;" ::: "memory");

    for (int ck = 0; ck < 36; ++ck) {
        if (ck <= 33)       asm volatile("cp.async.wait_group 2;" ::: "memory");
        else if (ck == 34)  asm volatile("cp.async.wait_group 1;" ::: "memory");
        else                asm volatile("cp.async.wait_group 0;" ::: "memory");
        __syncthreads();
        if (ck < 33) {
            stage(ck + 3);
            asm volatile("cp.async.commit_group;" ::: "memory");
        }

        uint32_t so = (uint32_t)(ck & 3)*STG;
        #pragma unroll
        for (int kh = 0; kh < 2; ++kh) {
            uint32_t ah[2][4], bh[4][4];
            ldsm4(ah[0], aBase + so + A_H + kh*32);
            ldsm4(ah[1], aBase + so + A_H + kh*32 + 16*ROWB);
            #pragma unroll
            for (int q = 0; q < 4; ++q)
                ldsm4(bh[q], bBase + so + B_H + kh*32 + q*16*ROWB);
            #pragma unroll
            for (int q = 0; q < 4; ++q)
                #pragma unroll
                for (int hf = 0; hf < 2; ++hf) {
                    int nt = 2*q + hf;
                    const uint32_t* bp = &bh[q][hf*2];
                    #pragma unroll
                    for (int mt = 0; mt < 2; ++mt)
                        mma_bf16(acc[mt][nt], ah[mt], bp);
                }
        }
    }
    __syncthreads();   // all reads of stage buffers done before sGB overwrites them

    // ---- epilogue: gather + blend into sGB [c128][132] ----
    float ga = 1.f / (1.f + __expf(-__ldg(bgam)));
    float ba = 1.f / (1.f + __expf(-__ldg(bbet)));

    #pragma unroll
    for (int mt = 0; mt < 2; ++mt)
        #pragma unroll
        for (int hi = 0; hi < 2; ++hi) {
            int m = wm*32 + mt*16 + g + hi*8;
            bool isG = (m < 64);
            int cc = m & 63;
            float blend = isG ? ga : ba;
            const float* sT = isG ? sTg : sTb;
            float cbv = __ldg(isG ? &cgb[cc] : &cbb[cc]);
            float sbv = __ldg(isG ? &sgb[cc] : &sbb[cc]);
            #pragma unroll
            for (int nt = 0; nt < 8; ++nt)
                #pragma unroll
                for (int lo = 0; lo < 2; ++lo) {
                    int px = wn*64 + nt*8 + tg*2 + lo;
                    float val = acc[mt][nt][hi*2 + lo];
                    float avg = cbv;
                    #pragma unroll
                    for (int tp = 0; tp < 9; ++tp) {
                        int ddy = tp / 3, ddx = tp - 3*ddy;
                        int rr = sR[ddy*132 + px + ddx];
                        if (rr < 5) avg += sT[(tp*5 + rr)*64 + cc];
                    }
                    sGB[m*132 + px] = blend*avg + (1.f - blend)*(val + sbv);
                }
        }
    __syncthreads();

    // ---- combine with instance-normed x (coalesced) ----
    for (int idx = t; idx < 8192; idx += 256) {
        int c = idx >> 7, px = idx & 127;
        int ch = (b << 6) + c;
        float xv = x_in[((size_t)ch << 14) + (y << 7) + px];
        float xn = (xv - __ldg(&g_mean[ch])) * __ldg(&g_rsig[ch]);
        float gf = sGB[c*132 + px];
        float bf = sGB[(c + 64)*132 + px];
        out[((size_t)ch << 14) + (y << 7) + px] = fmaf(xn, gf, xn) + bf;
    }
}

// ---------------- launch ----------------
extern "C" void kernel_launch(void* const* d_in, const int* in_sizes, int n_in,
                              void* d_out, int out_size) {
    const float* x      = (const float*)d_in[0];
    const float* segmap = (const float*)d_in[1];
    const float* codes  = (const float*)d_in[2];
    const float* mask   = (const float*)d_in[3];
    const float* fc_w   = (const float*)d_in[4];
    const float* fc_b   = (const float*)d_in[5];
    const float* cgw    = (const float*)d_in[6];
    const float* cgb    = (const float*)d_in[7];
    const float* cbw    = (const float*)d_in[8];
    const float* cbb    = (const float*)d_in[9];
    const float* ssw    = (const float*)d_in[10];
    const float* ssb    = (const float*)d_in[11];
    const float* sgw    = (const float*)d_in[12];
    const float* sgb    = (const float*)d_in[13];
    const float* sbw    = (const float*)d_in[14];
    const float* sbb    = (const float*)d_in[15];
    const float* bgam   = (const float*)d_in[16];
    const float* bbet   = (const float*)d_in[17];
    float* out = (float*)d_out;

    cudaFuncSetAttribute(final_kernel, cudaFuncAttributeMaxDynamicSharedMemorySize, DYN_BYTES);

    mu_kernel<<<B_*F_, 512>>>(codes, fc_w, fc_b);
    region_kernel<<<(B_*HH*WW + 255)/256, 256>>>(segmap);
    table_kernel<<<2880, 256>>>(cgw, cbw);
    stats_kernel<<<B_*C_, 256>>>(x);
    wprep_kernel<<<(9*128*128 + 255)/256, 256>>>(sgw, sbw);
    {
        dim3 g(4, 128, 4);
        sconv_kernel<<<g, 256>>>(mask, ssw, ssb);
    }
    {
        dim3 g(128, 4);
        final_kernel<<<g, 256, DYN_BYTES>>>(x, sgb, sbb, cgb, cbb, bgam, bbet, out);
    }
}

// round 7
// speedup vs baseline: 1.5988x; 1.5988x over previous
#include <cuda_runtime.h>
#include <cuda_bf16.h>
#include <math.h>
#include <stdint.h>

#define B_  4
#define C_  64
#define HH  128
#define WW  128
#define F_  5
#define L_  512
#define NH_ 128

// ---------------- device scratch ----------------
__device__ float g_mu[B_*F_*L_];
__device__ unsigned char g_rmap[B_*HH*WW];
__device__ float g_Tg[B_*9*F_*C_];               // [b][tap][f][c]
__device__ float g_Tb[B_*9*F_*C_];
__device__ __nv_bfloat16 g_act[(size_t)B_*HH*WW*NH_];  // NHWC bf16
__device__ __nv_bfloat16 g_Aw[9*128*128];        // [tap][c128][nh] bf16
__device__ float g_mean[B_*C_];
__device__ float g_rsig[B_*C_];

// ---------------- helpers ----------------
__device__ __forceinline__ uint32_t smem_u32(const void* p) {
    uint32_t a;
    asm("{ .reg .u64 t; cvta.to.shared.u64 t, %1; cvt.u32.u64 %0, t; }" : "=r"(a) : "l"(p));
    return a;
}
__device__ __forceinline__ void cpa16(uint32_t dst, const void* src, uint32_t ssz) {
    asm volatile("cp.async.ca.shared.global [%0], [%1], 16, %2;"
                 :: "r"(dst), "l"(src), "r"(ssz) : "memory");
}
__device__ __forceinline__ void ldsm4(uint32_t* r, uint32_t addr) {
    asm volatile("ldmatrix.sync.aligned.m8n8.x4.shared.b16 {%0,%1,%2,%3}, [%4];"
        : "=r"(r[0]), "=r"(r[1]), "=r"(r[2]), "=r"(r[3]) : "r"(addr));
}
__device__ __forceinline__ void mma_bf16(float* d, const uint32_t* a, const uint32_t* b) {
    asm volatile("mma.sync.aligned.m16n8k16.row.col.f32.bf16.bf16.f32 "
        "{%0,%1,%2,%3},{%4,%5,%6,%7},{%8,%9},{%0,%1,%2,%3};"
        : "+f"(d[0]), "+f"(d[1]), "+f"(d[2]), "+f"(d[3])
        : "r"(a[0]), "r"(a[1]), "r"(a[2]), "r"(a[3]), "r"(b[0]), "r"(b[1]));
}

// ---------------- mu = relu(codes @ fc_w^T + fc_b) ----------------
__global__ void mu_kernel(const float* __restrict__ codes,
                          const float* __restrict__ fc_w,
                          const float* __restrict__ fc_b) {
    __shared__ float sc[L_];
    int bf = blockIdx.x;
    int f = bf % F_;
    int k = threadIdx.x;
    sc[k] = codes[bf*L_ + k];
    __syncthreads();
    const float* wp = fc_w + ((size_t)f*L_ + k)*L_;
    float acc = fc_b[f*L_ + k];
    #pragma unroll 4
    for (int l = 0; l < L_; ++l) acc = fmaf(sc[l], wp[l], acc);
    g_mu[bf*L_ + k] = fmaxf(acc, 0.f);
}

// ---------------- region map ----------------
__global__ void region_kernel(const float* __restrict__ seg) {
    int p = blockIdx.x*256 + threadIdx.x;
    if (p >= B_*HH*WW) return;
    int b = p >> 14, pix = p & 16383;
    int r = 5;
    #pragma unroll
    for (int j = 0; j < F_; ++j)
        if (seg[(b*F_ + j)*16384 + pix] > 0.f) r = j;
    g_rmap[p] = (unsigned char)r;
}

// ---------------- tables T[b,tap,f,c] ----------------
__global__ void table_kernel(const float* __restrict__ cgw,
                             const float* __restrict__ cbw) {
    int gt = blockIdx.x*256 + threadIdx.x;
    int e = gt >> 5, lane = gt & 31;
    int tbl = e / 11520; int r = e - tbl*11520;
    int b = r / 2880;    int r2 = r - b*2880;
    int tap = r2 / 320;  int r3 = r2 - tap*320;
    int f = r3 >> 6;     int c = r3 & 63;
    int dy = tap / 3, dx = tap - dy*3;
    const float* w = tbl ? cbw : cgw;
    const float* m = g_mu + (b*F_ + f)*L_;
    float s = 0.f;
    for (int l = lane; l < L_; l += 32)
        s = fmaf(w[(((size_t)c*L_ + l)*3 + dy)*3 + dx], m[l], s);
    #pragma unroll
    for (int o = 16; o > 0; o >>= 1) s += __shfl_down_sync(0xffffffffu, s, o);
    if (lane == 0)
        (tbl ? g_Tb : g_Tg)[((b*9 + tap)*F_ + f)*64 + c] = s;
}

// ---------------- instance norm stats ----------------
__global__ void stats_kernel(const float* __restrict__ x) {
    int bc = blockIdx.x;
    const float* p = x + (size_t)bc*16384;
    float s = 0.f, s2 = 0.f;
    for (int i = threadIdx.x; i < 16384; i += 256) {
        float v = p[i]; s += v; s2 = fmaf(v, v, s2);
    }
    __shared__ float sh1[256], sh2[256];
    sh1[threadIdx.x] = s; sh2[threadIdx.x] = s2;
    __syncthreads();
    for (int o = 128; o > 0; o >>= 1) {
        if (threadIdx.x < o) { sh1[threadIdx.x] += sh1[threadIdx.x+o]; sh2[threadIdx.x] += sh2[threadIdx.x+o]; }
        __syncthreads();
    }
    if (threadIdx.x == 0) {
        float m = sh1[0] * (1.f/16384.f);
        float var = sh2[0] * (1.f/16384.f) - m*m;
        g_mean[bc] = m;
        g_rsig[bc] = rsqrtf(var + 1e-5f);
    }
}

// ---------------- weight prep: bf16, layout [tap][c128][nh] ----------------
__global__ void wprep_kernel(const float* __restrict__ sgw,
                             const float* __restrict__ sbw) {
    int idx = blockIdx.x*256 + threadIdx.x;
    if (idx >= 9*128*128) return;
    int nh = idx & 127, c = (idx >> 7) & 127, tap = idx >> 14;
    const float* src = (c < 64) ? sgw : sbw;
    float v = src[(((c & 63)*128) + nh)*9 + tap];
    g_Aw[idx] = __float2bfloat16_rn(v);
}

// ---------------- SPADE shared conv -> NHWC bf16 ----------------
__global__ void sconv_kernel(const float* __restrict__ mask,
                             const float* __restrict__ w,
                             const float* __restrict__ bias) {
    __shared__ float sw[NH_*27];
    __shared__ float smk[3][3][34];
    int t = threadIdx.x;
    int b = blockIdx.z, y = blockIdx.y, x0 = blockIdx.x*32;
    for (int i = t; i < NH_*27; i += 256) sw[i] = w[i];
    for (int i = t; i < 3*3*34; i += 256) {
        int ch = i / 102, rem = i - ch*102;
        int r = rem / 34, cx = rem - r*34;
        int gy = y + r - 1, gx = x0 + cx - 1;
        float v = 0.f;
        if ((unsigned)gy < 128u && (unsigned)gx < 128u)
            v = mask[((b*3 + ch) << 14) + (gy << 7) + gx];
        smk[ch][r][cx] = v;
    }
    __syncthreads();
    int px = t >> 3, g = t & 7;
    float mv[3][3][3];
    #pragma unroll
    for (int ch = 0; ch < 3; ++ch)
        #pragma unroll
        for (int r = 0; r < 3; ++r)
            #pragma unroll
            for (int d = 0; d < 3; ++d)
                mv[ch][r][d] = smk[ch][r][px + d];
    int nh0 = g*16;
    unsigned hw[8];
    #pragma unroll 2
    for (int k = 0; k < 16; ++k) {
        int nh = nh0 + k;
        float acc = __ldg(&bias[nh]);
        const float* wp = &sw[nh*27];
        #pragma unroll
        for (int ch = 0; ch < 3; ++ch)
            #pragma unroll
            for (int r = 0; r < 3; ++r)
                #pragma unroll
                for (int d = 0; d < 3; ++d)
                    acc = fmaf(mv[ch][r][d], wp[ch*9 + r*3 + d], acc);
        acc = fmaxf(acc, 0.f);
        unsigned hb = (unsigned)__bfloat16_as_ushort(__float2bfloat16_rn(acc));
        if (k & 1) hw[k>>1] |= hb << 16;
        else       hw[k>>1]  = hb;
    }
    size_t base = (((size_t)(b*128 + y))*128 + (x0 + px))*128 + nh0;
    uint4* dh = (uint4*)&g_act[base];
    dh[0] = make_uint4(hw[0], hw[1], hw[2], hw[3]);
    dh[1] = make_uint4(hw[4], hw[5], hw[6], hw[7]);
}

// ---------------- fused HMMA conv + table gather + blend + denorm ----------------
// block = 2 image rows (256 px), 256 threads (8 warps: 4M x 2N), M=128 couts.
// Single bf16 term; K = 1152 in 18 chunks of 64 (half-tap); 3-stage cp.async ring.
// Warp tile: 32 couts x 128 px. 128 MMA per warp per chunk.
// Stage rows of 144B (128B data + 16B pad, ldsm conflict-free: 36 banks stride).
#define ROWB   144
#define A_OFF  0
#define B_OFF  18432
#define STG    55296
#define OFF_TG 165888
#define OFF_TB 177408
#define OFF_R  188928
#define DYN_BYTES 189472
#define GBS    264          // sGB pixel stride (floats)

__global__ __launch_bounds__(256, 1) void final_kernel(
    const float* __restrict__ x_in,
    const float* __restrict__ sgb, const float* __restrict__ sbb,
    const float* __restrict__ cgb, const float* __restrict__ cbb,
    const float* __restrict__ bgam, const float* __restrict__ bbet,
    float* __restrict__ out)
{
    extern __shared__ char dsm[];
    uint32_t sb = smem_u32(dsm);
    float* sGB = (float*)dsm;                  // [128 c][264] epilogue (aliases stages)
    float* sTg = (float*)(dsm + OFF_TG);
    float* sTb = (float*)(dsm + OFF_TB);
    unsigned char* sR = (unsigned char*)(dsm + OFF_R);   // [4][132]

    int t = threadIdx.x, wid = t >> 5, lane = t & 31;
    int b = blockIdx.y, y0 = blockIdx.x * 2;
    int wm = wid >> 1, wn = wid & 1, g = lane >> 2, tg = lane & 3;

    // prologue: tables + region halo (rows y0-1 .. y0+2)
    for (int i = t; i < 2880; i += 256) {
        sTg[i] = g_Tg[b*2880 + i];
        sTb[i] = g_Tb[b*2880 + i];
    }
    for (int i = t; i < 4*132; i += 256) {
        int r = i / 132, cx = i - r*132;
        int gy = y0 - 1 + r, gx = cx - 1;
        unsigned char rr = 5;
        if (cx < 130 && (unsigned)gy < 128u && (unsigned)gx < 128u)
            rr = g_rmap[(b << 14) + (gy << 7) + gx];
        sR[i] = rr;
    }

    // ldmatrix lane address bases
    int rowA = wm*32 + (lane & 7) + ((lane >> 3) & 1)*8;
    int kbA  = (lane >> 4)*16;
    uint32_t aBase = sb + A_OFF + rowA*ROWB + kbA;
    int nB  = wn*128 + (lane & 7) + ((lane >> 4) & 1)*8;
    int kbB = ((lane >> 3) & 1)*16;
    uint32_t bBase = sb + B_OFF + nB*ROWB + kbB;

    // staging: chunk ck -> tap = ck>>1, kc = ck&1 (64 K values at koff = kc*64)
    auto stage = [&](int ck) {
        int s = ck % 3;
        int tap = ck >> 1, kc = ck & 1;
        int dyy = tap / 3, dxx = tap - 3*dyy;
        uint32_t base = sb + s*STG;
        int koff = kc*64;
        // A: 128 rows x 8 segs (16B)
        for (int i = t; i < 1024; i += 256) {
            int row = i >> 3, seg = i & 7;
            cpa16(base + A_OFF + row*ROWB + seg*16,
                  g_Aw + (size_t)tap*16384 + row*128 + koff + seg*8, 16);
        }
        // B: 256 px-rows x 8 segs
        for (int i = t; i < 2048; i += 256) {
            int row = i >> 3, seg = i & 7;
            int r = row >> 7, x = row & 127;
            int gy = y0 + r + dyy - 1, gx = x + dxx - 1;
            bool in = ((unsigned)gy < 128u) && ((unsigned)gx < 128u);
            size_t src = (((size_t)(b*128 + (in ? gy : 0)))*128 + (in ? gx : 0))*128 + koff + seg*8;
            cpa16(base + B_OFF + row*ROWB + seg*16, g_act + src, in ? 16u : 0u);
        }
    };

    float acc[2][16][4];
    #pragma unroll
    for (int mt = 0; mt < 2; ++mt)
        #pragma unroll
        for (int nt = 0; nt < 16; ++nt)
            #pragma unroll
            for (int ci = 0; ci < 4; ++ci) acc[mt][nt][ci] = 0.f;

    stage(0);
    asm volatile("cp.async.commit_group;" ::: "memory");
    stage(1);
    asm volatile("cp.async.commit_group;" ::: "memory");

    for (int ck = 0; ck < 18; ++ck) {
        if (ck < 17) asm volatile("cp.async.wait_group 1;" ::: "memory");
        else         asm volatile("cp.async.wait_group 0;" ::: "memory");
        __syncthreads();
        if (ck < 16) {
            stage(ck + 2);
            asm volatile("cp.async.commit_group;" ::: "memory");
        }

        uint32_t so = (uint32_t)(ck % 3)*STG;
        #pragma unroll
        for (int kh = 0; kh < 4; ++kh) {
            uint32_t ah[2][4], bh[8][4];
            ldsm4(ah[0], aBase + so + kh*32);
            ldsm4(ah[1], aBase + so + kh*32 + 16*ROWB);
            #pragma unroll
            for (int q = 0; q < 8; ++q)
                ldsm4(bh[q], bBase + so + kh*32 + q*16*ROWB);
            #pragma unroll
            for (int q = 0; q < 8; ++q)
                #pragma unroll
                for (int hf = 0; hf < 2; ++hf) {
                    int nt = 2*q + hf;
                    const uint32_t* bp = &bh[q][hf*2];
                    #pragma unroll
                    for (int mt = 0; mt < 2; ++mt)
                        mma_bf16(acc[mt][nt], ah[mt], bp);
                }
        }
    }
    __syncthreads();   // all stage-buffer reads done before sGB overwrites them

    // ---- epilogue: gather + blend into sGB [c128][264] ----
    float ga = 1.f / (1.f + __expf(-__ldg(bgam)));
    float ba = 1.f / (1.f + __expf(-__ldg(bbet)));

    #pragma unroll
    for (int mt = 0; mt < 2; ++mt)
        #pragma unroll
        for (int hi = 0; hi < 2; ++hi) {
            int m = wm*32 + mt*16 + g + hi*8;
            bool isG = (m < 64);
            int cc = m & 63;
            float blend = isG ? ga : ba;
            const float* sT = isG ? sTg : sTb;
            float cbv = __ldg(isG ? &cgb[cc] : &cbb[cc]);
            float sbv = __ldg(isG ? &sgb[cc] : &sbb[cc]);
            #pragma unroll
            for (int nt = 0; nt < 16; ++nt)
                #pragma unroll
                for (int lo = 0; lo < 2; ++lo) {
                    int px = wn*128 + nt*8 + tg*2 + lo;
                    int r = px >> 7, x = px & 127;
                    float val = acc[mt][nt][hi*2 + lo];
                    float avg = cbv;
                    #pragma unroll
                    for (int tp = 0; tp < 9; ++tp) {
                        int ddy = tp / 3, ddx = tp - 3*ddy;
                        int rr = sR[(r + ddy)*132 + x + ddx];
                        if (rr < 5) avg += sT[(tp*5 + rr)*64 + cc];
                    }
                    sGB[m*GBS + px] = blend*avg + (1.f - blend)*(val + sbv);
                }
        }
    __syncthreads();

    // ---- combine with instance-normed x (coalesced) ----
    for (int idx = t; idx < 16384; idx += 256) {
        int c = idx >> 8, p = idx & 255;
        int r = p >> 7, x = p & 127, y = y0 + r;
        int ch = (b << 6) + c;
        float xv = x_in[((size_t)ch << 14) + (y << 7) + x];
        float xn = (xv - __ldg(&g_mean[ch])) * __ldg(&g_rsig[ch]);
        float gf = sGB[c*GBS + p];
        float bf = sGB[(c + 64)*GBS + p];
        out[((size_t)ch << 14) + (y << 7) + x] = fmaf(xn, gf, xn) + bf;
    }
}

// ---------------- launch ----------------
extern "C" void kernel_launch(void* const* d_in, const int* in_sizes, int n_in,
                              void* d_out, int out_size) {
    const float* x      = (const float*)d_in[0];
    const float* segmap = (const float*)d_in[1];
    const float* codes  = (const float*)d_in[2];
    const float* mask   = (const float*)d_in[3];
    const float* fc_w   = (const float*)d_in[4];
    const float* fc_b   = (const float*)d_in[5];
    const float* cgw    = (const float*)d_in[6];
    const float* cgb    = (const float*)d_in[7];
    const float* cbw    = (const float*)d_in[8];
    const float* cbb    = (const float*)d_in[9];
    const float* ssw    = (const float*)d_in[10];
    const float* ssb    = (const float*)d_in[11];
    const float* sgw    = (const float*)d_in[12];
    const float* sgb    = (const float*)d_in[13];
    const float* sbw    = (const float*)d_in[14];
    const float* sbb    = (const float*)d_in[15];
    const float* bgam   = (const float*)d_in[16];
    const float* bbet   = (const float*)d_in[17];
    float* out = (float*)d_out;

    cudaFuncSetAttribute(final_kernel, cudaFuncAttributeMaxDynamicSharedMemorySize, DYN_BYTES);

    mu_kernel<<<B_*F_, 512>>>(codes, fc_w, fc_b);
    region_kernel<<<(B_*HH*WW + 255)/256, 256>>>(segmap);
    table_kernel<<<2880, 256>>>(cgw, cbw);
    stats_kernel<<<B_*C_, 256>>>(x);
    wprep_kernel<<<(9*128*128 + 255)/256, 256>>>(sgw, sbw);
    {
        dim3 g(4, 128, 4);
        sconv_kernel<<<g, 256>>>(mask, ssw, ssb);
    }
    {
        dim3 g(64, 4);
        final_kernel<<<g, 256, DYN_BYTES>>>(x, sgb, sbb, cgb, cbb, bgam, bbet, out);
    }
}

// round 8
// speedup vs baseline: 1.6493x; 1.0316x over previous
#include <cuda_runtime.h>
#include <cuda_bf16.h>
#include <math.h>
#include <stdint.h>

#define B_  4
#define C_  64
#define HH  128
#define WW  128
#define F_  5
#define L_  512
#define NH_ 128

// ---------------- device scratch ----------------
__device__ float g_mu[B_*F_*L_];
__device__ unsigned char g_rmap[B_*HH*WW];
__device__ float g_Tg[B_*9*F_*C_];               // [b][tap][f][c]
__device__ float g_Tb[B_*9*F_*C_];
__device__ __nv_bfloat16 g_act[(size_t)B_*HH*WW*NH_];  // NHWC bf16
__device__ __nv_bfloat16 g_Aw[9*128*128];        // [tap][c128][nh] bf16
__device__ float g_mean[B_*C_];
__device__ float g_rsig[B_*C_];

// ---------------- helpers ----------------
__device__ __forceinline__ uint32_t smem_u32(const void* p) {
    uint32_t a;
    asm("{ .reg .u64 t; cvta.to.shared.u64 t, %1; cvt.u32.u64 %0, t; }" : "=r"(a) : "l"(p));
    return a;
}
__device__ __forceinline__ void cpa16(uint32_t dst, const void* src, uint32_t ssz) {
    asm volatile("cp.async.ca.shared.global [%0], [%1], 16, %2;"
                 :: "r"(dst), "l"(src), "r"(ssz) : "memory");
}
__device__ __forceinline__ void ldsm4(uint32_t* r, uint32_t addr) {
    asm volatile("ldmatrix.sync.aligned.m8n8.x4.shared.b16 {%0,%1,%2,%3}, [%4];"
        : "=r"(r[0]), "=r"(r[1]), "=r"(r[2]), "=r"(r[3]) : "r"(addr));
}
__device__ __forceinline__ void mma_bf16(float* d, const uint32_t* a, const uint32_t* b) {
    asm volatile("mma.sync.aligned.m16n8k16.row.col.f32.bf16.bf16.f32 "
        "{%0,%1,%2,%3},{%4,%5,%6,%7},{%8,%9},{%0,%1,%2,%3};"
        : "+f"(d[0]), "+f"(d[1]), "+f"(d[2]), "+f"(d[3])
        : "r"(a[0]), "r"(a[1]), "r"(a[2]), "r"(a[3]), "r"(b[0]), "r"(b[1]));
}

// ---------------- mu = relu(codes @ fc_w^T + fc_b) ----------------
__global__ void mu_kernel(const float* __restrict__ codes,
                          const float* __restrict__ fc_w,
                          const float* __restrict__ fc_b) {
    __shared__ float sc[L_];
    int bf = blockIdx.x;
    int f = bf % F_;
    int k = threadIdx.x;
    sc[k] = codes[bf*L_ + k];
    __syncthreads();
    const float* wp = fc_w + ((size_t)f*L_ + k)*L_;
    float acc = fc_b[f*L_ + k];
    #pragma unroll 4
    for (int l = 0; l < L_; ++l) acc = fmaf(sc[l], wp[l], acc);
    g_mu[bf*L_ + k] = fmaxf(acc, 0.f);
}

// ---------------- region map ----------------
__global__ void region_kernel(const float* __restrict__ seg) {
    int p = blockIdx.x*256 + threadIdx.x;
    if (p >= B_*HH*WW) return;
    int b = p >> 14, pix = p & 16383;
    int r = 5;
    #pragma unroll
    for (int j = 0; j < F_; ++j)
        if (seg[(b*F_ + j)*16384 + pix] > 0.f) r = j;
    g_rmap[p] = (unsigned char)r;
}

// ---------------- tables T[b,tap,f,c] ----------------
__global__ void table_kernel(const float* __restrict__ cgw,
                             const float* __restrict__ cbw) {
    int gt = blockIdx.x*256 + threadIdx.x;
    int e = gt >> 5, lane = gt & 31;
    int tbl = e / 11520; int r = e - tbl*11520;
    int b = r / 2880;    int r2 = r - b*2880;
    int tap = r2 / 320;  int r3 = r2 - tap*320;
    int f = r3 >> 6;     int c = r3 & 63;
    int dy = tap / 3, dx = tap - dy*3;
    const float* w = tbl ? cbw : cgw;
    const float* m = g_mu + (b*F_ + f)*L_;
    float s = 0.f;
    for (int l = lane; l < L_; l += 32)
        s = fmaf(w[(((size_t)c*L_ + l)*3 + dy)*3 + dx], m[l], s);
    #pragma unroll
    for (int o = 16; o > 0; o >>= 1) s += __shfl_down_sync(0xffffffffu, s, o);
    if (lane == 0)
        (tbl ? g_Tb : g_Tg)[((b*9 + tap)*F_ + f)*64 + c] = s;
}

// ---------------- instance norm stats (float4) ----------------
__global__ void stats_kernel(const float* __restrict__ x) {
    int bc = blockIdx.x;
    const float4* p = (const float4*)(x + (size_t)bc*16384);
    float s = 0.f, s2 = 0.f;
    for (int i = threadIdx.x; i < 4096; i += 256) {
        float4 v = p[i];
        s += v.x + v.y + v.z + v.w;
        s2 = fmaf(v.x, v.x, fmaf(v.y, v.y, fmaf(v.z, v.z, fmaf(v.w, v.w, s2))));
    }
    __shared__ float sh1[256], sh2[256];
    sh1[threadIdx.x] = s; sh2[threadIdx.x] = s2;
    __syncthreads();
    for (int o = 128; o > 0; o >>= 1) {
        if (threadIdx.x < o) { sh1[threadIdx.x] += sh1[threadIdx.x+o]; sh2[threadIdx.x] += sh2[threadIdx.x+o]; }
        __syncthreads();
    }
    if (threadIdx.x == 0) {
        float m = sh1[0] * (1.f/16384.f);
        float var = sh2[0] * (1.f/16384.f) - m*m;
        g_mean[bc] = m;
        g_rsig[bc] = rsqrtf(var + 1e-5f);
    }
}

// ---------------- weight prep: bf16, layout [tap][c128][nh] ----------------
__global__ void wprep_kernel(const float* __restrict__ sgw,
                             const float* __restrict__ sbw) {
    int idx = blockIdx.x*256 + threadIdx.x;
    if (idx >= 9*128*128) return;
    int nh = idx & 127, c = (idx >> 7) & 127, tap = idx >> 14;
    const float* src = (c < 64) ? sgw : sbw;
    float v = src[(((c & 63)*128) + nh)*9 + tap];
    g_Aw[idx] = __float2bfloat16_rn(v);
}

// ---------------- SPADE shared conv -> NHWC bf16 ----------------
__global__ void sconv_kernel(const float* __restrict__ mask,
                             const float* __restrict__ w,
                             const float* __restrict__ bias) {
    __shared__ float sw[NH_*27];
    __shared__ float smk[3][3][34];
    int t = threadIdx.x;
    int b = blockIdx.z, y = blockIdx.y, x0 = blockIdx.x*32;
    for (int i = t; i < NH_*27; i += 256) sw[i] = w[i];
    for (int i = t; i < 3*3*34; i += 256) {
        int ch = i / 102, rem = i - ch*102;
        int r = rem / 34, cx = rem - r*34;
        int gy = y + r - 1, gx = x0 + cx - 1;
        float v = 0.f;
        if ((unsigned)gy < 128u && (unsigned)gx < 128u)
            v = mask[((b*3 + ch) << 14) + (gy << 7) + gx];
        smk[ch][r][cx] = v;
    }
    __syncthreads();
    int px = t >> 3, g = t & 7;
    float mv[3][3][3];
    #pragma unroll
    for (int ch = 0; ch < 3; ++ch)
        #pragma unroll
        for (int r = 0; r < 3; ++r)
            #pragma unroll
            for (int d = 0; d < 3; ++d)
                mv[ch][r][d] = smk[ch][r][px + d];
    int nh0 = g*16;
    unsigned hw[8];
    #pragma unroll 2
    for (int k = 0; k < 16; ++k) {
        int nh = nh0 + k;
        float acc = __ldg(&bias[nh]);
        const float* wp = &sw[nh*27];
        #pragma unroll
        for (int ch = 0; ch < 3; ++ch)
            #pragma unroll
            for (int r = 0; r < 3; ++r)
                #pragma unroll
                for (int d = 0; d < 3; ++d)
                    acc = fmaf(mv[ch][r][d], wp[ch*9 + r*3 + d], acc);
        acc = fmaxf(acc, 0.f);
        unsigned hb = (unsigned)__bfloat16_as_ushort(__float2bfloat16_rn(acc));
        if (k & 1) hw[k>>1] |= hb << 16;
        else       hw[k>>1]  = hb;
    }
    size_t base = (((size_t)(b*128 + y))*128 + (x0 + px))*128 + nh0;
    uint4* dh = (uint4*)&g_act[base];
    dh[0] = make_uint4(hw[0], hw[1], hw[2], hw[3]);
    dh[1] = make_uint4(hw[4], hw[5], hw[6], hw[7]);
}

// ---------------- fused HMMA conv + table gather + blend + denorm ----------------
// block = 2 image rows (256 px), 512 threads (16 warps: 4M x 4N), M=128 couts.
// Warp tile: 32 couts x 64 px. K = 1152 in 18 chunks of 64; 3-stage cp.async ring.
#define ROWB   144
#define A_OFF  0
#define B_OFF  18432
#define STG    55296
#define OFF_TG 165888
#define OFF_TB 177408
#define OFF_R  188928
#define DYN_BYTES 189472
#define GBS    264          // sGB pixel stride (floats)

__global__ __launch_bounds__(512, 1) void final_kernel(
    const float* __restrict__ x_in,
    const float* __restrict__ sgb, const float* __restrict__ sbb,
    const float* __restrict__ cgb, const float* __restrict__ cbb,
    const float* __restrict__ bgam, const float* __restrict__ bbet,
    float* __restrict__ out)
{
    extern __shared__ char dsm[];
    uint32_t sb = smem_u32(dsm);
    float* sGB = (float*)dsm;                  // [128 c][264] epilogue (aliases stages)
    float* sTg = (float*)(dsm + OFF_TG);
    float* sTb = (float*)(dsm + OFF_TB);
    unsigned char* sR = (unsigned char*)(dsm + OFF_R);   // [4][132]

    int t = threadIdx.x, wid = t >> 5, lane = t & 31;
    int b = blockIdx.y, y0 = blockIdx.x * 2;
    int wm = wid >> 2, wn = wid & 3, g = lane >> 2, tg = lane & 3;

    // prologue: tables + region halo (rows y0-1 .. y0+2)
    for (int i = t; i < 2880; i += 512) {
        sTg[i] = g_Tg[b*2880 + i];
        sTb[i] = g_Tb[b*2880 + i];
    }
    for (int i = t; i < 4*132; i += 512) {
        int r = i / 132, cx = i - r*132;
        int gy = y0 - 1 + r, gx = cx - 1;
        unsigned char rr = 5;
        if (cx < 130 && (unsigned)gy < 128u && (unsigned)gx < 128u)
            rr = g_rmap[(b << 14) + (gy << 7) + gx];
        sR[i] = rr;
    }

    // ldmatrix lane address bases
    int rowA = wm*32 + (lane & 7) + ((lane >> 3) & 1)*8;
    int kbA  = (lane >> 4)*16;
    uint32_t aBase = sb + A_OFF + rowA*ROWB + kbA;
    int nB  = wn*64 + (lane & 7) + ((lane >> 4) & 1)*8;
    int kbB = ((lane >> 3) & 1)*16;
    uint32_t bBase = sb + B_OFF + nB*ROWB + kbB;

    // staging: chunk ck -> tap = ck>>1, kc = ck&1 (64 K values at koff = kc*64)
    auto stage = [&](int ck) {
        int s = ck % 3;
        int tap = ck >> 1, kc = ck & 1;
        int dyy = tap / 3, dxx = tap - 3*dyy;
        uint32_t base = sb + s*STG;
        int koff = kc*64;
        // A: 128 rows x 8 segs (16B)
        for (int i = t; i < 1024; i += 512) {
            int row = i >> 3, seg = i & 7;
            cpa16(base + A_OFF + row*ROWB + seg*16,
                  g_Aw + (size_t)tap*16384 + row*128 + koff + seg*8, 16);
        }
        // B: 256 px-rows x 8 segs
        for (int i = t; i < 2048; i += 512) {
            int row = i >> 3, seg = i & 7;
            int r = row >> 7, x = row & 127;
            int gy = y0 + r + dyy - 1, gx = x + dxx - 1;
            bool in = ((unsigned)gy < 128u) && ((unsigned)gx < 128u);
            size_t src = (((size_t)(b*128 + (in ? gy : 0)))*128 + (in ? gx : 0))*128 + koff + seg*8;
            cpa16(base + B_OFF + row*ROWB + seg*16, g_act + src, in ? 16u : 0u);
        }
    };

    float acc[2][8][4];
    #pragma unroll
    for (int mt = 0; mt < 2; ++mt)
        #pragma unroll
        for (int nt = 0; nt < 8; ++nt)
            #pragma unroll
            for (int ci = 0; ci < 4; ++ci) acc[mt][nt][ci] = 0.f;

    stage(0);
    asm volatile("cp.async.commit_group;" ::: "memory");
    stage(1);
    asm volatile("cp.async.commit_group;" ::: "memory");

    for (int ck = 0; ck < 18; ++ck) {
        if (ck < 17) asm volatile("cp.async.wait_group 1;" ::: "memory");
        else         asm volatile("cp.async.wait_group 0;" ::: "memory");
        __syncthreads();
        if (ck < 16) {
            stage(ck + 2);
            asm volatile("cp.async.commit_group;" ::: "memory");
        }

        uint32_t so = (uint32_t)(ck % 3)*STG;
        #pragma unroll
        for (int kh = 0; kh < 4; ++kh) {
            uint32_t ah[2][4], bh[4][4];
            ldsm4(ah[0], aBase + so + kh*32);
            ldsm4(ah[1], aBase + so + kh*32 + 16*ROWB);
            #pragma unroll
            for (int q = 0; q < 4; ++q)
                ldsm4(bh[q], bBase + so + kh*32 + q*16*ROWB);
            #pragma unroll
            for (int q = 0; q < 4; ++q)
                #pragma unroll
                for (int hf = 0; hf < 2; ++hf) {
                    int nt = 2*q + hf;
                    const uint32_t* bp = &bh[q][hf*2];
                    #pragma unroll
                    for (int mt = 0; mt < 2; ++mt)
                        mma_bf16(acc[mt][nt], ah[mt], bp);
                }
        }
    }
    __syncthreads();   // all stage-buffer reads done before sGB overwrites them

    // ---- epilogue: gather + blend into sGB [c128][264] ----
    float ga = 1.f / (1.f + __expf(-__ldg(bgam)));
    float ba = 1.f / (1.f + __expf(-__ldg(bbet)));

    #pragma unroll
    for (int mt = 0; mt < 2; ++mt)
        #pragma unroll
        for (int hi = 0; hi < 2; ++hi) {
            int m = wm*32 + mt*16 + g + hi*8;
            bool isG = (m < 64);
            int cc = m & 63;
            float blend = isG ? ga : ba;
            const float* sT = isG ? sTg : sTb;
            float cbv = __ldg(isG ? &cgb[cc] : &cbb[cc]);
            float sbv = __ldg(isG ? &sgb[cc] : &sbb[cc]);
            #pragma unroll
            for (int nt = 0; nt < 8; ++nt)
                #pragma unroll
                for (int lo = 0; lo < 2; ++lo) {
                    int px = wn*64 + nt*8 + tg*2 + lo;
                    int r = px >> 7, x = px & 127;
                    float val = acc[mt][nt][hi*2 + lo];
                    float avg = cbv;
                    #pragma unroll
                    for (int tp = 0; tp < 9; ++tp) {
                        int ddy = tp / 3, ddx = tp - 3*ddy;
                        int rr = sR[(r + ddy)*132 + x + ddx];
                        if (rr < 5) avg += sT[(tp*5 + rr)*64 + cc];
                    }
                    sGB[m*GBS + px] = blend*avg + (1.f - blend)*(val + sbv);
                }
        }
    __syncthreads();

    // ---- combine with instance-normed x (coalesced) ----
    for (int idx = t; idx < 16384; idx += 512) {
        int c = idx >> 8, p = idx & 255;
        int r = p >> 7, x = p & 127, y = y0 + r;
        int ch = (b << 6) + c;
        float xv = x_in[((size_t)ch << 14) + (y << 7) + x];
        float xn = (xv - __ldg(&g_mean[ch])) * __ldg(&g_rsig[ch]);
        float gf = sGB[c*GBS + p];
        float bf = sGB[(c + 64)*GBS + p];
        out[((size_t)ch << 14) + (y << 7) + x] = fmaf(xn, gf, xn) + bf;
    }
}

// ---------------- launch ----------------
extern "C" void kernel_launch(void* const* d_in, const int* in_sizes, int n_in,
                              void* d_out, int out_size) {
    const float* x      = (const float*)d_in[0];
    const float* segmap = (const float*)d_in[1];
    const float* codes  = (const float*)d_in[2];
    const float* mask   = (const float*)d_in[3];
    const float* fc_w   = (const float*)d_in[4];
    const float* fc_b   = (const float*)d_in[5];
    const float* cgw    = (const float*)d_in[6];
    const float* cgb    = (const float*)d_in[7];
    const float* cbw    = (const float*)d_in[8];
    const float* cbb    = (const float*)d_in[9];
    const float* ssw    = (const float*)d_in[10];
    const float* ssb    = (const float*)d_in[11];
    const float* sgw    = (const float*)d_in[12];
    const float* sgb    = (const float*)d_in[13];
    const float* sbw    = (const float*)d_in[14];
    const float* sbb    = (const float*)d_in[15];
    const float* bgam   = (const float*)d_in[16];
    const float* bbet   = (const float*)d_in[17];
    float* out = (float*)d_out;

    cudaFuncSetAttribute(final_kernel, cudaFuncAttributeMaxDynamicSharedMemorySize, DYN_BYTES);

    mu_kernel<<<B_*F_, 512>>>(codes, fc_w, fc_b);
    region_kernel<<<(B_*HH*WW + 255)/256, 256>>>(segmap);
    table_kernel<<<2880, 256>>>(cgw, cbw);
    stats_kernel<<<B_*C_, 256>>>(x);
    wprep_kernel<<<(9*128*128 + 255)/256, 256>>>(sgw, sbw);
    {
        dim3 g(4, 128, 4);
        sconv_kernel<<<g, 256>>>(mask, ssw, ssb);
    }
    {
        dim3 g(64, 4);
        final_kernel<<<g, 512, DYN_BYTES>>>(x, sgb, sbb, cgb, cbb, bgam, bbet, out);
    }
}

// round 9
// speedup vs baseline: 2.6834x; 1.6269x over previous
#include <cuda_runtime.h>
#include <cuda_bf16.h>
#include <math.h>
#include <stdint.h>

#define B_  4
#define C_  64
#define HH  128
#define WW  128
#define F_  5
#define L_  512
#define NH_ 128

// ---------------- device scratch ----------------
__device__ float g_mu[B_*F_*L_];
__device__ unsigned char g_rmap[B_*HH*WW];
__device__ float g_Tg[B_*9*F_*C_];               // [b][tap][f][c]
__device__ float g_Tb[B_*9*F_*C_];
__device__ __nv_bfloat16 g_act[(size_t)B_*HH*WW*NH_];  // NHWC bf16
__device__ __nv_bfloat16 g_Aw[9*128*128];        // [tap][c128][nh] bf16
__device__ float g_mean[B_*C_];
__device__ float g_rsig[B_*C_];

// ---------------- helpers ----------------
__device__ __forceinline__ uint32_t smem_u32(const void* p) {
    uint32_t a;
    asm("{ .reg .u64 t; cvta.to.shared.u64 t, %1; cvt.u32.u64 %0, t; }" : "=r"(a) : "l"(p));
    return a;
}
__device__ __forceinline__ void cpa16(uint32_t dst, const void* src, uint32_t ssz) {
    asm volatile("cp.async.ca.shared.global [%0], [%1], 16, %2;"
                 :: "r"(dst), "l"(src), "r"(ssz) : "memory");
}
__device__ __forceinline__ void ldsm4(uint32_t* r, uint32_t addr) {
    asm volatile("ldmatrix.sync.aligned.m8n8.x4.shared.b16 {%0,%1,%2,%3}, [%4];"
        : "=r"(r[0]), "=r"(r[1]), "=r"(r[2]), "=r"(r[3]) : "r"(addr));
}
__device__ __forceinline__ void mma_bf16(float* d, const uint32_t* a, const uint32_t* b) {
    asm volatile("mma.sync.aligned.m16n8k16.row.col.f32.bf16.bf16.f32 "
        "{%0,%1,%2,%3},{%4,%5,%6,%7},{%8,%9},{%0,%1,%2,%3};"
        : "+f"(d[0]), "+f"(d[1]), "+f"(d[2]), "+f"(d[3])
        : "r"(a[0]), "r"(a[1]), "r"(a[2]), "r"(a[3]), "r"(b[0]), "r"(b[1]));
}

// ---------------- mu = relu(codes @ fc_w^T + fc_b), warp per output ----------------
// outputs: 20 bf x 512 k = 10240 warps; 256 threads/block -> 1280 blocks
__global__ void mu_kernel(const float* __restrict__ codes,
                          const float* __restrict__ fc_w,
                          const float* __restrict__ fc_b) {
    int gw = blockIdx.x*8 + (threadIdx.x >> 5);
    int lane = threadIdx.x & 31;
    int bf = gw >> 9, k = gw & 511;
    int f = bf % F_;
    const float4* wp = (const float4*)(fc_w + ((size_t)f*L_ + k)*L_);
    const float4* cp = (const float4*)(codes + (size_t)bf*L_);
    float s = 0.f;
    #pragma unroll
    for (int i = 0; i < 4; ++i) {
        float4 w4 = wp[lane + i*32];
        float4 c4 = cp[lane + i*32];
        s = fmaf(w4.x, c4.x, fmaf(w4.y, c4.y, fmaf(w4.z, c4.z, fmaf(w4.w, c4.w, s))));
    }
    #pragma unroll
    for (int o = 16; o > 0; o >>= 1) s += __shfl_down_sync(0xffffffffu, s, o);
    if (lane == 0)
        g_mu[bf*L_ + k] = fmaxf(s + fc_b[f*L_ + k], 0.f);
}

// ---------------- region map ----------------
__global__ void region_kernel(const float* __restrict__ seg) {
    int p = blockIdx.x*256 + threadIdx.x;
    if (p >= B_*HH*WW) return;
    int b = p >> 14, pix = p & 16383;
    int r = 5;
    #pragma unroll
    for (int j = 0; j < F_; ++j)
        if (seg[(b*F_ + j)*16384 + pix] > 0.f) r = j;
    g_rmap[p] = (unsigned char)r;
}

// ---------------- tables: warp per (tbl,b,f,c), all 9 taps together ----------------
// 2*4*5*64 = 2560 warps; 256 threads/block -> 320 blocks
__global__ void table_kernel(const float* __restrict__ cgw,
                             const float* __restrict__ cbw) {
    int gw = blockIdx.x*8 + (threadIdx.x >> 5);
    int lane = threadIdx.x & 31;
    int tbl = gw / 1280;  int r = gw - tbl*1280;
    int b = r / 320;      int r2 = r - b*320;
    int f = r2 >> 6;      int c = r2 & 63;
    const float* w = (tbl ? cbw : cgw) + (size_t)c*L_*9;
    const float* m = g_mu + (b*F_ + f)*L_;
    float s[9];
    #pragma unroll
    for (int tp = 0; tp < 9; ++tp) s[tp] = 0.f;
    for (int l = lane; l < L_; l += 32) {
        float mv = m[l];
        const float* wl = w + l*9;
        #pragma unroll
        for (int tp = 0; tp < 9; ++tp) s[tp] = fmaf(wl[tp], mv, s[tp]);
    }
    #pragma unroll
    for (int tp = 0; tp < 9; ++tp) {
        float v = s[tp];
        #pragma unroll
        for (int o = 16; o > 0; o >>= 1) v += __shfl_down_sync(0xffffffffu, v, o);
        if (lane == 0)
            (tbl ? g_Tb : g_Tg)[((b*9 + tp)*F_ + f)*64 + c] = v;
    }
}

// ---------------- instance norm stats (float4, 1024 threads) ----------------
__global__ void stats_kernel(const float* __restrict__ x) {
    int bc = blockIdx.x;
    const float4* p = (const float4*)(x + (size_t)bc*16384);
    float s = 0.f, s2 = 0.f;
    for (int i = threadIdx.x; i < 4096; i += 1024) {
        float4 v = p[i];
        s += v.x + v.y + v.z + v.w;
        s2 = fmaf(v.x, v.x, fmaf(v.y, v.y, fmaf(v.z, v.z, fmaf(v.w, v.w, s2))));
    }
    __shared__ float sh1[1024], sh2[1024];
    sh1[threadIdx.x] = s; sh2[threadIdx.x] = s2;
    __syncthreads();
    for (int o = 512; o > 0; o >>= 1) {
        if (threadIdx.x < o) { sh1[threadIdx.x] += sh1[threadIdx.x+o]; sh2[threadIdx.x] += sh2[threadIdx.x+o]; }
        __syncthreads();
    }
    if (threadIdx.x == 0) {
        float m = sh1[0] * (1.f/16384.f);
        float var = sh2[0] * (1.f/16384.f) - m*m;
        g_mean[bc] = m;
        g_rsig[bc] = rsqrtf(var + 1e-5f);
    }
}

// ---------------- weight prep: bf16, layout [tap][c128][nh] ----------------
__global__ void wprep_kernel(const float* __restrict__ sgw,
                             const float* __restrict__ sbw) {
    int idx = blockIdx.x*256 + threadIdx.x;
    if (idx >= 9*128*128) return;
    int nh = idx & 127, c = (idx >> 7) & 127, tap = idx >> 14;
    const float* src = (c < 64) ? sgw : sbw;
    float v = src[(((c & 63)*128) + nh)*9 + tap];
    g_Aw[idx] = __float2bfloat16_rn(v);
}

// ---------------- SPADE shared conv -> NHWC bf16 ----------------
__global__ void sconv_kernel(const float* __restrict__ mask,
                             const float* __restrict__ w,
                             const float* __restrict__ bias) {
    __shared__ float sw[NH_*27];
    __shared__ float smk[3][3][34];
    int t = threadIdx.x;
    int b = blockIdx.z, y = blockIdx.y, x0 = blockIdx.x*32;
    for (int i = t; i < NH_*27; i += 256) sw[i] = w[i];
    for (int i = t; i < 3*3*34; i += 256) {
        int ch = i / 102, rem = i - ch*102;
        int r = rem / 34, cx = rem - r*34;
        int gy = y + r - 1, gx = x0 + cx - 1;
        float v = 0.f;
        if ((unsigned)gy < 128u && (unsigned)gx < 128u)
            v = mask[((b*3 + ch) << 14) + (gy << 7) + gx];
        smk[ch][r][cx] = v;
    }
    __syncthreads();
    int px = t >> 3, g = t & 7;
    float mv[3][3][3];
    #pragma unroll
    for (int ch = 0; ch < 3; ++ch)
        #pragma unroll
        for (int r = 0; r < 3; ++r)
            #pragma unroll
            for (int d = 0; d < 3; ++d)
                mv[ch][r][d] = smk[ch][r][px + d];
    int nh0 = g*16;
    unsigned hw[8];
    #pragma unroll 2
    for (int k = 0; k < 16; ++k) {
        int nh = nh0 + k;
        float acc = __ldg(&bias[nh]);
        const float* wp = &sw[nh*27];
        #pragma unroll
        for (int ch = 0; ch < 3; ++ch)
            #pragma unroll
            for (int r = 0; r < 3; ++r)
                #pragma unroll
                for (int d = 0; d < 3; ++d)
                    acc = fmaf(mv[ch][r][d], wp[ch*9 + r*3 + d], acc);
        acc = fmaxf(acc, 0.f);
        unsigned hb = (unsigned)__bfloat16_as_ushort(__float2bfloat16_rn(acc));
        if (k & 1) hw[k>>1] |= hb << 16;
        else       hw[k>>1]  = hb;
    }
    size_t base = (((size_t)(b*128 + y))*128 + (x0 + px))*128 + nh0;
    uint4* dh = (uint4*)&g_act[base];
    dh[0] = make_uint4(hw[0], hw[1], hw[2], hw[3]);
    dh[1] = make_uint4(hw[4], hw[5], hw[6], hw[7]);
}

// ---------------- fused HMMA conv + table gather + blend + denorm ----------------
// block = 2 image rows (256 px), 512 threads (16 warps: 4M x 4N), M=128 couts.
// Warp tile: 32 couts x 64 px. K = 1152 in 18 chunks of 64; 3-stage cp.async ring.
#define ROWB   144
#define A_OFF  0
#define B_OFF  18432
#define STG    55296
#define OFF_TG 165888
#define OFF_TB 177408
#define OFF_R  188928
#define DYN_BYTES 189472
#define GBS    264          // sGB pixel stride (floats)

__global__ __launch_bounds__(512, 1) void final_kernel(
    const float* __restrict__ x_in,
    const float* __restrict__ sgb, const float* __restrict__ sbb,
    const float* __restrict__ cgb, const float* __restrict__ cbb,
    const float* __restrict__ bgam, const float* __restrict__ bbet,
    float* __restrict__ out)
{
    extern __shared__ char dsm[];
    uint32_t sb = smem_u32(dsm);
    float* sGB = (float*)dsm;                  // [128 c][264] epilogue (aliases stages)
    float* sTg = (float*)(dsm + OFF_TG);
    float* sTb = (float*)(dsm + OFF_TB);
    unsigned char* sR = (unsigned char*)(dsm + OFF_R);   // [4][132]

    int t = threadIdx.x, wid = t >> 5, lane = t & 31;
    int b = blockIdx.y, y0 = blockIdx.x * 2;
    int wm = wid >> 2, wn = wid & 3, g = lane >> 2, tg = lane & 3;

    // prologue: tables + region halo (rows y0-1 .. y0+2)
    for (int i = t; i < 2880; i += 512) {
        sTg[i] = g_Tg[b*2880 + i];
        sTb[i] = g_Tb[b*2880 + i];
    }
    for (int i = t; i < 4*132; i += 512) {
        int r = i / 132, cx = i - r*132;
        int gy = y0 - 1 + r, gx = cx - 1;
        unsigned char rr = 5;
        if (cx < 130 && (unsigned)gy < 128u && (unsigned)gx < 128u)
            rr = g_rmap[(b << 14) + (gy << 7) + gx];
        sR[i] = rr;
    }

    // ldmatrix lane address bases
    int rowA = wm*32 + (lane & 7) + ((lane >> 3) & 1)*8;
    int kbA  = (lane >> 4)*16;
    uint32_t aBase = sb + A_OFF + rowA*ROWB + kbA;
    int nB  = wn*64 + (lane & 7) + ((lane >> 4) & 1)*8;
    int kbB = ((lane >> 3) & 1)*16;
    uint32_t bBase = sb + B_OFF + nB*ROWB + kbB;

    // staging: chunk ck -> tap = ck>>1, kc = ck&1 (64 K values at koff = kc*64)
    auto stage = [&](int ck) {
        int s = ck % 3;
        int tap = ck >> 1, kc = ck & 1;
        int dyy = tap / 3, dxx = tap - 3*dyy;
        uint32_t base = sb + s*STG;
        int koff = kc*64;
        // A: 128 rows x 8 segs (16B)
        for (int i = t; i < 1024; i += 512) {
            int row = i >> 3, seg = i & 7;
            cpa16(base + A_OFF + row*ROWB + seg*16,
                  g_Aw + (size_t)tap*16384 + row*128 + koff + seg*8, 16);
        }
        // B: 256 px-rows x 8 segs
        for (int i = t; i < 2048; i += 512) {
            int row = i >> 3, seg = i & 7;
            int r = row >> 7, x = row & 127;
            int gy = y0 + r + dyy - 1, gx = x + dxx - 1;
            bool in = ((unsigned)gy < 128u) && ((unsigned)gx < 128u);
            size_t src = (((size_t)(b*128 + (in ? gy : 0)))*128 + (in ? gx : 0))*128 + koff + seg*8;
            cpa16(base + B_OFF + row*ROWB + seg*16, g_act + src, in ? 16u : 0u);
        }
    };

    float acc[2][8][4];
    #pragma unroll
    for (int mt = 0; mt < 2; ++mt)
        #pragma unroll
        for (int nt = 0; nt < 8; ++nt)
            #pragma unroll
            for (int ci = 0; ci < 4; ++ci) acc[mt][nt][ci] = 0.f;

    stage(0);
    asm volatile("cp.async.commit_group;" ::: "memory");
    stage(1);
    asm volatile("cp.async.commit_group;" ::: "memory");

    for (int ck = 0; ck < 18; ++ck) {
        if (ck < 17) asm volatile("cp.async.wait_group 1;" ::: "memory");
        else         asm volatile("cp.async.wait_group 0;" ::: "memory");
        __syncthreads();
        if (ck < 16) {
            stage(ck + 2);
            asm volatile("cp.async.commit_group;" ::: "memory");
        }

        uint32_t so = (uint32_t)(ck % 3)*STG;
        #pragma unroll
        for (int kh = 0; kh < 4; ++kh) {
            uint32_t ah[2][4], bh[4][4];
            ldsm4(ah[0], aBase + so + kh*32);
            ldsm4(ah[1], aBase + so + kh*32 + 16*ROWB);
            #pragma unroll
            for (int q = 0; q < 4; ++q)
                ldsm4(bh[q], bBase + so + kh*32 + q*16*ROWB);
            #pragma unroll
            for (int q = 0; q < 4; ++q)
                #pragma unroll
                for (int hf = 0; hf < 2; ++hf) {
                    int nt = 2*q + hf;
                    const uint32_t* bp = &bh[q][hf*2];
                    #pragma unroll
                    for (int mt = 0; mt < 2; ++mt)
                        mma_bf16(acc[mt][nt], ah[mt], bp);
                }
        }
    }
    __syncthreads();   // all stage-buffer reads done before sGB overwrites them

    // ---- epilogue: gather + blend into sGB [c128][264] ----
    float ga = 1.f / (1.f + __expf(-__ldg(bgam)));
    float ba = 1.f / (1.f + __expf(-__ldg(bbet)));

    #pragma unroll
    for (int mt = 0; mt < 2; ++mt)
        #pragma unroll
        for (int hi = 0; hi < 2; ++hi) {
            int m = wm*32 + mt*16 + g + hi*8;
            bool isG = (m < 64);
            int cc = m & 63;
            float blend = isG ? ga : ba;
            const float* sT = isG ? sTg : sTb;
            float cbv = __ldg(isG ? &cgb[cc] : &cbb[cc]);
            float sbv = __ldg(isG ? &sgb[cc] : &sbb[cc]);
            #pragma unroll
            for (int nt = 0; nt < 8; ++nt)
                #pragma unroll
                for (int lo = 0; lo < 2; ++lo) {
                    int px = wn*64 + nt*8 + tg*2 + lo;
                    int r = px >> 7, x = px & 127;
                    float val = acc[mt][nt][hi*2 + lo];
                    float avg = cbv;
                    #pragma unroll
                    for (int tp = 0; tp < 9; ++tp) {
                        int ddy = tp / 3, ddx = tp - 3*ddy;
                        int rr = sR[(r + ddy)*132 + x + ddx];
                        if (rr < 5) avg += sT[(tp*5 + rr)*64 + cc];
                    }
                    sGB[m*GBS + px] = blend*avg + (1.f - blend)*(val + sbv);
                }
        }
    __syncthreads();

    // ---- combine with instance-normed x (coalesced) ----
    for (int idx = t; idx < 16384; idx += 512) {
        int c = idx >> 8, p = idx & 255;
        int r = p >> 7, x = p & 127, y = y0 + r;
        int ch = (b << 6) + c;
        float xv = x_in[((size_t)ch << 14) + (y << 7) + x];
        float xn = (xv - __ldg(&g_mean[ch])) * __ldg(&g_rsig[ch]);
        float gf = sGB[c*GBS + p];
        float bf = sGB[(c + 64)*GBS + p];
        out[((size_t)ch << 14) + (y << 7) + x] = fmaf(xn, gf, xn) + bf;
    }
}

// ---------------- launch ----------------
extern "C" void kernel_launch(void* const* d_in, const int* in_sizes, int n_in,
                              void* d_out, int out_size) {
    const float* x      = (const float*)d_in[0];
    const float* segmap = (const float*)d_in[1];
    const float* codes  = (const float*)d_in[2];
    const float* mask   = (const float*)d_in[3];
    const float* fc_w   = (const float*)d_in[4];
    const float* fc_b   = (const float*)d_in[5];
    const float* cgw    = (const float*)d_in[6];
    const float* cgb    = (const float*)d_in[7];
    const float* cbw    = (const float*)d_in[8];
    const float* cbb    = (const float*)d_in[9];
    const float* ssw    = (const float*)d_in[10];
    const float* ssb    = (const float*)d_in[11];
    const float* sgw    = (const float*)d_in[12];
    const float* sgb    = (const float*)d_in[13];
    const float* sbw    = (const float*)d_in[14];
    const float* sbb    = (const float*)d_in[15];
    const float* bgam   = (const float*)d_in[16];
    const float* bbet   = (const float*)d_in[17];
    float* out = (float*)d_out;

    cudaFuncSetAttribute(final_kernel, cudaFuncAttributeMaxDynamicSharedMemorySize, DYN_BYTES);

    mu_kernel<<<1280, 256>>>(codes, fc_w, fc_b);
    region_kernel<<<(B_*HH*WW + 255)/256, 256>>>(segmap);
    stats_kernel<<<B_*C_, 1024>>>(x);
    wprep_kernel<<<(9*128*128 + 255)/256, 256>>>(sgw, sbw);
    {
        dim3 g(4, 128, 4);
        sconv_kernel<<<g, 256>>>(mask, ssw, ssb);
    }
    table_kernel<<<320, 256>>>(cgw, cbw);
    {
        dim3 g(64, 4);
        final_kernel<<<g, 512, DYN_BYTES>>>(x, sgb, sbb, cgb, cbb, bgam, bbet, out);
    }
}

// round 10
// speedup vs baseline: 2.8574x; 1.0649x over previous
#include <cuda_runtime.h>
#include <cuda_bf16.h>
#include <math.h>
#include <stdint.h>

#define B_  4
#define C_  64
#define HH  128
#define WW  128
#define F_  5
#define L_  512
#define NH_ 128

// ---------------- device scratch ----------------
__device__ float g_mu[B_*F_*L_];
__device__ unsigned char g_rmap[B_*HH*WW];
__device__ float g_Tg[B_*9*F_*C_];               // [b][tap][f][c]
__device__ float g_Tb[B_*9*F_*C_];
__device__ __nv_bfloat16 g_act[(size_t)B_*HH*WW*NH_];  // NHWC bf16
__device__ __nv_bfloat16 g_Aw[9*128*128];        // [tap][c128][nh] bf16
__device__ float g_mean[B_*C_];
__device__ float g_rsig[B_*C_];
__device__ float g_blend[2];

// ---------------- helpers ----------------
__device__ __forceinline__ uint32_t smem_u32(const void* p) {
    uint32_t a;
    asm("{ .reg .u64 t; cvta.to.shared.u64 t, %1; cvt.u32.u64 %0, t; }" : "=r"(a) : "l"(p));
    return a;
}
__device__ __forceinline__ void cpa16(uint32_t dst, const void* src, uint32_t ssz) {
    asm volatile("cp.async.ca.shared.global [%0], [%1], 16, %2;"
                 :: "r"(dst), "l"(src), "r"(ssz) : "memory");
}
__device__ __forceinline__ void ldsm4(uint32_t* r, uint32_t addr) {
    asm volatile("ldmatrix.sync.aligned.m8n8.x4.shared.b16 {%0,%1,%2,%3}, [%4];"
        : "=r"(r[0]), "=r"(r[1]), "=r"(r[2]), "=r"(r[3]) : "r"(addr));
}
__device__ __forceinline__ void mma_bf16(float* d, const uint32_t* a, const uint32_t* b) {
    asm volatile("mma.sync.aligned.m16n8k16.row.col.f32.bf16.bf16.f32 "
        "{%0,%1,%2,%3},{%4,%5,%6,%7},{%8,%9},{%0,%1,%2,%3};"
        : "+f"(d[0]), "+f"(d[1]), "+f"(d[2]), "+f"(d[3])
        : "r"(a[0]), "r"(a[1]), "r"(a[2]), "r"(a[3]), "r"(b[0]), "r"(b[1]));
}

// ================= K1: fused preps (mu | region | stats | wprep) =================
// grid 2368 x 256
__global__ void prep_fused(const float* __restrict__ codes,
                           const float* __restrict__ fc_w,
                           const float* __restrict__ fc_b,
                           const float* __restrict__ seg,
                           const float* __restrict__ x,
                           const float* __restrict__ sgw,
                           const float* __restrict__ sbw) {
    __shared__ float sh1[256], sh2[256];
    int bid = blockIdx.x, t = threadIdx.x;
    if (bid < 1280) {
        // mu: warp per output
        int gw = bid*8 + (t >> 5);
        int lane = t & 31;
        int bf = gw >> 9, k = gw & 511;
        int f = bf % F_;
        const float4* wp = (const float4*)(fc_w + ((size_t)f*L_ + k)*L_);
        const float4* cp = (const float4*)(codes + (size_t)bf*L_);
        float s = 0.f;
        #pragma unroll
        for (int i = 0; i < 4; ++i) {
            float4 w4 = wp[lane + i*32];
            float4 c4 = cp[lane + i*32];
            s = fmaf(w4.x, c4.x, fmaf(w4.y, c4.y, fmaf(w4.z, c4.z, fmaf(w4.w, c4.w, s))));
        }
        #pragma unroll
        for (int o = 16; o > 0; o >>= 1) s += __shfl_down_sync(0xffffffffu, s, o);
        if (lane == 0)
            g_mu[bf*L_ + k] = fmaxf(s + fc_b[f*L_ + k], 0.f);
    } else if (bid < 1536) {
        int p = (bid - 1280)*256 + t;
        int b = p >> 14, pix = p & 16383;
        int r = 5;
        #pragma unroll
        for (int j = 0; j < F_; ++j)
            if (seg[(b*F_ + j)*16384 + pix] > 0.f) r = j;
        g_rmap[p] = (unsigned char)r;
    } else if (bid < 1792) {
        int bc = bid - 1536;
        const float4* p = (const float4*)(x + (size_t)bc*16384);
        float s = 0.f, s2 = 0.f;
        for (int i = t; i < 4096; i += 256) {
            float4 v = p[i];
            s += v.x + v.y + v.z + v.w;
            s2 = fmaf(v.x, v.x, fmaf(v.y, v.y, fmaf(v.z, v.z, fmaf(v.w, v.w, s2))));
        }
        sh1[t] = s; sh2[t] = s2;
        __syncthreads();
        for (int o = 128; o > 0; o >>= 1) {
            if (t < o) { sh1[t] += sh1[t+o]; sh2[t] += sh2[t+o]; }
            __syncthreads();
        }
        if (t == 0) {
            float m = sh1[0] * (1.f/16384.f);
            float var = sh2[0] * (1.f/16384.f) - m*m;
            g_mean[bc] = m;
            g_rsig[bc] = rsqrtf(var + 1e-5f);
        }
    } else {
        int idx = (bid - 1792)*256 + t;
        int nh = idx & 127, c = (idx >> 7) & 127, tap = idx >> 14;
        const float* src = (c < 64) ? sgw : sbw;
        float v = src[(((c & 63)*128) + nh)*9 + tap];
        g_Aw[idx] = __float2bfloat16_rn(v);
    }
}

// ================= K2: sconv | table =================
// grid 2368 x 256 (2048 sconv + 320 table)
__global__ void sconv_table(const float* __restrict__ mask,
                            const float* __restrict__ w,
                            const float* __restrict__ bias,
                            const float* __restrict__ cgw,
                            const float* __restrict__ cbw) {
    __shared__ float sw[NH_*27];
    __shared__ float smk[3][3][34];
    int bid = blockIdx.x, t = threadIdx.x;
    if (bid < 2048) {
        int xblk = bid & 3, y = (bid >> 2) & 127, b = bid >> 9;
        int x0 = xblk*32;
        for (int i = t; i < NH_*27; i += 256) sw[i] = w[i];
        for (int i = t; i < 3*3*34; i += 256) {
            int ch = i / 102, rem = i - ch*102;
            int r = rem / 34, cx = rem - r*34;
            int gy = y + r - 1, gx = x0 + cx - 1;
            float v = 0.f;
            if ((unsigned)gy < 128u && (unsigned)gx < 128u)
                v = mask[((b*3 + ch) << 14) + (gy << 7) + gx];
            smk[ch][r][cx] = v;
        }
        __syncthreads();
        int px = t >> 3, g = t & 7;
        float mv[3][3][3];
        #pragma unroll
        for (int ch = 0; ch < 3; ++ch)
            #pragma unroll
            for (int r = 0; r < 3; ++r)
                #pragma unroll
                for (int d = 0; d < 3; ++d)
                    mv[ch][r][d] = smk[ch][r][px + d];
        int nh0 = g*16;
        unsigned hw[8];
        #pragma unroll 2
        for (int k = 0; k < 16; ++k) {
            int nh = nh0 + k;
            float acc = __ldg(&bias[nh]);
            const float* wp = &sw[nh*27];
            #pragma unroll
            for (int ch = 0; ch < 3; ++ch)
                #pragma unroll
                for (int r = 0; r < 3; ++r)
                    #pragma unroll
                    for (int d = 0; d < 3; ++d)
                        acc = fmaf(mv[ch][r][d], wp[ch*9 + r*3 + d], acc);
            acc = fmaxf(acc, 0.f);
            unsigned hb = (unsigned)__bfloat16_as_ushort(__float2bfloat16_rn(acc));
            if (k & 1) hw[k>>1] |= hb << 16;
            else       hw[k>>1]  = hb;
        }
        size_t base = (((size_t)(b*128 + y))*128 + (x0 + px))*128 + nh0;
        uint4* dh = (uint4*)&g_act[base];
        dh[0] = make_uint4(hw[0], hw[1], hw[2], hw[3]);
        dh[1] = make_uint4(hw[4], hw[5], hw[6], hw[7]);
    } else {
        int gw = (bid - 2048)*8 + (t >> 5);
        int lane = t & 31;
        int tbl = gw / 1280;  int r = gw - tbl*1280;
        int b = r / 320;      int r2 = r - b*320;
        int f = r2 >> 6;      int c = r2 & 63;
        const float* wv = (tbl ? cbw : cgw) + (size_t)c*L_*9;
        const float* m = g_mu + (b*F_ + f)*L_;
        float s[9];
        #pragma unroll
        for (int tp = 0; tp < 9; ++tp) s[tp] = 0.f;
        for (int l = lane; l < L_; l += 32) {
            float mv = m[l];
            const float* wl = wv + l*9;
            #pragma unroll
            for (int tp = 0; tp < 9; ++tp) s[tp] = fmaf(wl[tp], mv, s[tp]);
        }
        #pragma unroll
        for (int tp = 0; tp < 9; ++tp) {
            float v = s[tp];
            #pragma unroll
            for (int o = 16; o > 0; o >>= 1) v += __shfl_down_sync(0xffffffffu, v, o);
            if (lane == 0)
                (tbl ? g_Tb : g_Tg)[((b*9 + tp)*F_ + f)*64 + c] = v;
        }
    }
}

// ================= K3: blend scalars =================
__global__ void blend_kernel(const float* __restrict__ bgam,
                             const float* __restrict__ bbet) {
    if (threadIdx.x == 0) {
        g_blend[0] = 1.f / (1.f + __expf(-bgam[0]));
        g_blend[1] = 1.f / (1.f + __expf(-bbet[0]));
    }
}

// ================= K4: fused HMMA conv + gather + blend + denorm =================
// block = 2 out rows (256 px), 512 thr (16 warps, 4M x 4N), M = 128 couts (gamma||beta).
// Persistent actv buffer: 4 halo rows x 130 px x 128 ch (one load),
// all 9 taps read B from it at shifted offsets; only weights pipelined (3-stage).
#define ROWB    144          // weight stage row stride (couts)
#define PXB     272          // actv pixel stride (256B data + 16 pad)
#define OFF_TB  11520
#define OFF_R   23040
#define ACT_OFF 23680
#define WOFF    165120       // 23680 + 520*272
#define WSTG    18432        // 128 * 144
#define DYN_BYTES 220416     // WOFF + 3*WSTG
#define GBS     264

__global__ __launch_bounds__(512, 1) void final_kernel(
    const float* __restrict__ x_in,
    const float* __restrict__ sgb, const float* __restrict__ sbb,
    const float* __restrict__ cgb, const float* __restrict__ cbb,
    float* __restrict__ out)
{
    extern __shared__ char dsm[];
    uint32_t sb = smem_u32(dsm);
    float* sTg = (float*)dsm;
    float* sTb = (float*)(dsm + OFF_TB);
    unsigned char* sR = (unsigned char*)(dsm + OFF_R);   // [4][132]
    float* sGB = (float*)(dsm + ACT_OFF);                // epilogue aliases actv buffer

    int t = threadIdx.x, wid = t >> 5, lane = t & 31;
    int b = blockIdx.y, y0 = blockIdx.x * 2;
    int wm = wid >> 2, wn = wid & 3, g = lane >> 2, tg = lane & 3;

    // prologue: tables + region halo
    for (int i = t; i < 2880; i += 512) {
        sTg[i] = g_Tg[b*2880 + i];
        sTb[i] = g_Tb[b*2880 + i];
    }
    for (int i = t; i < 4*132; i += 512) {
        int r = i / 132, cx = i - r*132;
        int gy = y0 - 1 + r, gx = cx - 1;
        unsigned char rr = 5;
        if (cx < 130 && (unsigned)gy < 128u && (unsigned)gx < 128u)
            rr = g_rmap[(b << 14) + (gy << 7) + gx];
        sR[i] = rr;
    }

    // ldmatrix lane address bases
    int rowA = wm*32 + (lane & 7) + ((lane >> 3) & 1)*8;
    int kbA  = (lane >> 4)*16;
    uint32_t aBase = sb + WOFF + rowA*ROWB + kbA;
    int rB  = wn >> 1;                                    // out-row of this warp
    int x0l = (wn & 1)*64 + (lane & 7) + ((lane >> 4) & 1)*8;
    int kbB = ((lane >> 3) & 1)*16;
    uint32_t bBase = sb + ACT_OFF + (uint32_t)(rB*130 + x0l)*PXB + kbB;

    // one-time actv staging: 4 rows x 130 px x 128 ch
    {
        for (int i = t; i < 8320; i += 512) {
            int seg = i & 15, e = i >> 4;
            int srow = e / 130, pxh = e - srow*130;
            int gy = y0 + srow - 1, gx = pxh - 1;
            bool in = ((unsigned)gy < 128u) && ((unsigned)gx < 128u);
            size_t src = (((size_t)(b*128 + (in ? gy : 0)))*128 + (in ? gx : 0))*128 + seg*8;
            cpa16(sb + ACT_OFF + (uint32_t)e*PXB + seg*16, g_act + src, in ? 16u : 0u);
        }
    }
    asm volatile("cp.async.commit_group;" ::: "memory");

    // weight staging: ws = h*9 + tap (h = ch-half, tap), ring of 3
    auto stageW = [&](int ws) {
        int slot = ws % 3, h = ws / 9, tap = ws % 9;
        for (int i = t; i < 1024; i += 512) {
            int row = i >> 3, seg = i & 7;
            cpa16(sb + WOFF + slot*WSTG + row*ROWB + seg*16,
                  g_Aw + (size_t)tap*16384 + row*128 + h*64 + seg*8, 16);
        }
    };

    float acc[2][8][4];
    #pragma unroll
    for (int mt = 0; mt < 2; ++mt)
        #pragma unroll
        for (int nt = 0; nt < 8; ++nt)
            #pragma unroll
            for (int ci = 0; ci < 4; ++ci) acc[mt][nt][ci] = 0.f;

    stageW(0);
    asm volatile("cp.async.commit_group;" ::: "memory");
    stageW(1);
    asm volatile("cp.async.commit_group;" ::: "memory");

    for (int ws = 0; ws < 18; ++ws) {
        if (ws < 17) asm volatile("cp.async.wait_group 1;" ::: "memory");
        else         asm volatile("cp.async.wait_group 0;" ::: "memory");
        __syncthreads();
        if (ws < 16) {
            stageW(ws + 2);
            asm volatile("cp.async.commit_group;" ::: "memory");
        }

        int h = ws / 9, tap = ws % 9;
        int dy = tap / 3, dx = tap - 3*dy;
        uint32_t so = (uint32_t)(ws % 3)*WSTG;
        uint32_t bTap = bBase + (uint32_t)(dy*130 + dx)*PXB + h*128;

        #pragma unroll
        for (int kh = 0; kh < 4; ++kh) {
            uint32_t ah[2][4], bh[4][4];
            ldsm4(ah[0], aBase + so + kh*32);
            ldsm4(ah[1], aBase + so + kh*32 + 16*ROWB);
            #pragma unroll
            for (int q = 0; q < 4; ++q)
                ldsm4(bh[q], bTap + kh*32 + q*16*PXB);
            #pragma unroll
            for (int q = 0; q < 4; ++q)
                #pragma unroll
                for (int hf = 0; hf < 2; ++hf) {
                    int nt = 2*q + hf;
                    const uint32_t* bp = &bh[q][hf*2];
                    #pragma unroll
                    for (int mt = 0; mt < 2; ++mt)
                        mma_bf16(acc[mt][nt], ah[mt], bp);
                }
        }
    }
    __syncthreads();   // all actv/weight reads done before sGB overwrites

    // ---- epilogue: gather + blend into sGB [c128][264] ----
    float ga = g_blend[0];
    float ba = g_blend[1];

    #pragma unroll
    for (int mt = 0; mt < 2; ++mt)
        #pragma unroll
        for (int hi = 0; hi < 2; ++hi) {
            int m = wm*32 + mt*16 + g + hi*8;
            bool isG = (m < 64);
            int cc = m & 63;
            float blend = isG ? ga : ba;
            const float* sT = isG ? sTg : sTb;
            float cbv = __ldg(isG ? &cgb[cc] : &cbb[cc]);
            float sbv = __ldg(isG ? &sgb[cc] : &sbb[cc]);
            #pragma unroll
            for (int nt = 0; nt < 8; ++nt)
                #pragma unroll
                for (int lo = 0; lo < 2; ++lo) {
                    int px = wn*64 + nt*8 + tg*2 + lo;
                    int r = px >> 7, x = px & 127;
                    float val = acc[mt][nt][hi*2 + lo];
                    float avg = cbv;
                    #pragma unroll
                    for (int tp = 0; tp < 9; ++tp) {
                        int ddy = tp / 3, ddx = tp - 3*ddy;
                        int rr = sR[(r + ddy)*132 + x + ddx];
                        if (rr < 5) avg += sT[(tp*5 + rr)*64 + cc];
                    }
                    sGB[m*GBS + px] = blend*avg + (1.f - blend)*(val + sbv);
                }
        }
    __syncthreads();

    // ---- combine with instance-normed x (coalesced) ----
    for (int idx = t; idx < 16384; idx += 512) {
        int c = idx >> 8, p = idx & 255;
        int r = p >> 7, x = p & 127, y = y0 + r;
        int ch = (b << 6) + c;
        float xv = x_in[((size_t)ch << 14) + (y << 7) + x];
        float xn = (xv - __ldg(&g_mean[ch])) * __ldg(&g_rsig[ch]);
        float gf = sGB[c*GBS + p];
        float bf = sGB[(c + 64)*GBS + p];
        out[((size_t)ch << 14) + (y << 7) + x] = fmaf(xn, gf, xn) + bf;
    }
}

// ---------------- launch ----------------
extern "C" void kernel_launch(void* const* d_in, const int* in_sizes, int n_in,
                              void* d_out, int out_size) {
    const float* x      = (const float*)d_in[0];
    const float* segmap = (const float*)d_in[1];
    const float* codes  = (const float*)d_in[2];
    const float* mask   = (const float*)d_in[3];
    const float* fc_w   = (const float*)d_in[4];
    const float* fc_b   = (const float*)d_in[5];
    const float* cgw    = (const float*)d_in[6];
    const float* cgb    = (const float*)d_in[7];
    const float* cbw    = (const float*)d_in[8];
    const float* cbb    = (const float*)d_in[9];
    const float* ssw    = (const float*)d_in[10];
    const float* ssb    = (const float*)d_in[11];
    const float* sgw    = (const float*)d_in[12];
    const float* sgb    = (const float*)d_in[13];
    const float* sbw    = (const float*)d_in[14];
    const float* sbb    = (const float*)d_in[15];
    const float* bgam   = (const float*)d_in[16];
    const float* bbet   = (const float*)d_in[17];
    float* out = (float*)d_out;

    cudaFuncSetAttribute(final_kernel, cudaFuncAttributeMaxDynamicSharedMemorySize, DYN_BYTES);

    prep_fused<<<2368, 256>>>(codes, fc_w, fc_b, segmap, x, sgw, sbw);
    sconv_table<<<2368, 256>>>(mask, ssw, ssb, cgw, cbw);
    blend_kernel<<<1, 32>>>(bgam, bbet);
    {
        dim3 g(64, 4);
        final_kernel<<<g, 512, DYN_BYTES>>>(x, sgb, sbb, cgb, cbb, out);
    }
}